// round 10
// baseline (speedup 1.0000x reference)
#include <cuda_runtime.h>

#define BATCH 2048
#define TT    512
#define HID   64
#define NB    7       // rows per CTA (296 CTAs = exactly 2 per SM)
#define NCTA  296
#define NTHR  256

typedef unsigned long long u64;

__device__ __forceinline__ u64 ffma2(u64 a, u64 b, u64 c) {
    u64 d;
    asm("fma.rn.f32x2 %0, %1, %2, %3;" : "=l"(d) : "l"(a), "l"(b), "l"(c));
    return d;
}

__device__ __forceinline__ float sum2(u64 v) {
    float lo, hi;
    asm("mov.b64 {%0, %1}, %2;" : "=f"(lo), "=f"(hi) : "l"(v));
    return lo + hi;
}

__device__ __forceinline__ float tanh_fast(float v) {
    float r;
    asm("tanh.approx.f32 %0, %1;" : "=f"(r) : "f"(v));
    return r;
}

__global__ __launch_bounds__(NTHR, 2)
void lstm_kernel(const float* __restrict__ x,
                 const float* __restrict__ W_ih,
                 const float* __restrict__ W_hh,
                 const float* __restrict__ b_ih,
                 const float* __restrict__ b_hh,
                 const float* __restrict__ W_d,
                 const float* __restrict__ b_d,
                 float* __restrict__ out) {
    __shared__ float x_s[NB][TT];        // 14 KB
    __shared__ float h_s[2][NB][HID];    // 3.5 KB, ping-pong on t parity

    const int tid  = threadIdx.x;
    const int lane = tid & 31;
    const int warp = tid >> 5;                 // 0..7
    const int q    = lane >> 3;                // k-quarter 0..3 == finalized gate id
    const int m    = (warp << 3) | (lane & 7); // hidden unit 0..63
    const int fcol = m + 64 * q;               // gate column this thread finalizes
    // branchless activation: act(v) = s0 + s1*tanh(sc*v); gate 2 (g) is tanh
    const float s0 = (q == 2) ? 0.0f : 0.5f;
    const float s1 = (q == 2) ? 1.0f : 0.5f;
    const float sc = (q == 2) ? 1.0f : 0.5f;
    const bool hi2 = (q >= 2);
    const bool odd = (q & 1);
    const bool isQ0 = (q == 0);

    const int row0 = blockIdx.x * NB;

    // --- weights: k-quarter (16 values) of all 4 gate columns of unit m ---
    u64 wq[4][8];                              // 32 u64 = 64 regs
#pragma unroll
    for (int j = 0; j < 4; j++) {
        const ulonglong2* p =
            reinterpret_cast<const ulonglong2*>(W_hh + (m + 64 * j) * HID + q * 16);
#pragma unroll
        for (int v = 0; v < 4; v++) {
            ulonglong2 u = p[v];
            wq[j][2 * v + 0] = u.x;
            wq[j][2 * v + 1] = u.y;
        }
    }
    const float bias = b_ih[fcol] + b_hh[fcol];
    const float wih  = W_ih[fcol];
    const int khoff  = q * 16;

    // --- stage x slab (coalesced; clamp rows past BATCH) ---
    for (int i = tid; i < NB * TT; i += NTHR) {
        int r = i / TT;
        int t = i % TT;
        int gr = row0 + r;
        if (gr > BATCH - 1) gr = BATCH - 1;
        x_s[r][t] = x[gr * TT + t];
    }
    // init read-buffer 0 (step 0 reads buf 0)
    for (int i = tid; i < NB * HID; i += NTHR)
        ((float*)h_s[0])[i] = 0.0f;

    // c state: q==0 threads own c for (row, unit m)
    float c[NB];
#pragma unroll
    for (int r = 0; r < NB; r++) c[r] = 0.0f;

    __syncthreads();

    for (int t = 0; t < TT; t++) {
        const float* hr = &h_s[t & 1][0][0];
        float*       hw = &h_s[(t + 1) & 1][0][0];

#pragma unroll
        for (int r = 0; r < NB; r++) {
            const float xv = x_s[r][t];

            // 4 back-to-back LDS.128: this k-quarter of h row r (broadcast per q-group)
            ulonglong2 hv[4];
#pragma unroll
            for (int v = 0; v < 4; v++)
                hv[v] = *reinterpret_cast<const ulonglong2*>(hr + r * HID + khoff + v * 4);

            u64 a0 = 0ull, a1 = 0ull, a2 = 0ull, a3 = 0ull;
#pragma unroll
            for (int v = 0; v < 4; v++) {
                a0 = ffma2(wq[0][2 * v + 0], hv[v].x, a0);
                a0 = ffma2(wq[0][2 * v + 1], hv[v].y, a0);
                a1 = ffma2(wq[1][2 * v + 0], hv[v].x, a1);
                a1 = ffma2(wq[1][2 * v + 1], hv[v].y, a1);
                a2 = ffma2(wq[2][2 * v + 0], hv[v].x, a2);
                a2 = ffma2(wq[2][2 * v + 1], hv[v].y, a2);
                a3 = ffma2(wq[3][2 * v + 0], hv[v].x, a3);
                a3 = ffma2(wq[3][2 * v + 1], hv[v].y, a3);
            }
            float p0 = sum2(a0), p1 = sum2(a1), p2 = sum2(a2), p3 = sum2(a3);

            // ---- reduce-scatter over the 4 k-quarters (convergent, verified R9) ----
            float sendA = hi2 ? p0 : p2;
            float sendB = hi2 ? p1 : p3;
            float rA = __shfl_xor_sync(0xffffffffu, sendA, 16);
            float rB = __shfl_xor_sync(0xffffffffu, sendB, 16);
            float sA = (hi2 ? p2 : p0) + rA;
            float sB = (hi2 ? p3 : p1) + rB;
            float send2 = odd ? sA : sB;
            float rc = __shfl_xor_sync(0xffffffffu, send2, 8);
            float totp = (odd ? sB : sA) + rc;      // full preact of gate q, unit m

            // activation (branchless per-gate constants)
            float tot = fmaf(xv, wih, bias) + totp;
            float act = fmaf(s1, tanh_fast(sc * tot), s0);

            // ---- gather f,g,o to the q=0 thread (convergent) ----
            float r_f = __shfl_xor_sync(0xffffffffu, act, 8);   // q0 <- q1 (f)
            float r_g = __shfl_xor_sync(0xffffffffu, act, 16);  // q0 <- q2 (g)
            float r_o = __shfl_xor_sync(0xffffffffu, act, 24);  // q0 <- q3 (o)

            if (isQ0) {   // act == i gate here
                c[r] = fmaf(r_f, c[r], act * r_g);
                hw[r * HID + m] = r_o * tanh_fast(c[r]);
            }
        }
        __syncthreads();   // single barrier per step (double-buffered h)
    }

    // ---------- final projection: h_T lives in buffer (TT)&1 == 0 ----------
    if (tid < NB && row0 + tid < BATCH) {
        float s = b_d[0];
#pragma unroll
        for (int mm = 0; mm < HID; mm++)
            s = fmaf(h_s[0][tid][mm], W_d[mm], s);
        out[row0 + tid] = s;
    }
}

extern "C" void kernel_launch(void* const* d_in, const int* in_sizes, int n_in,
                              void* d_out, int out_size) {
    const float* x    = (const float*)d_in[0];
    const float* W_ih = (const float*)d_in[1];
    const float* W_hh = (const float*)d_in[2];
    const float* b_ih = (const float*)d_in[3];
    const float* b_hh = (const float*)d_in[4];
    const float* W_d  = (const float*)d_in[5];
    const float* b_d  = (const float*)d_in[6];
    float* out = (float*)d_out;

    lstm_kernel<<<NCTA, NTHR>>>(x, W_ih, W_hh, b_ih, b_hh, W_d, b_d, out);
}

// round 11
// speedup vs baseline: 1.0782x; 1.0782x over previous
#include <cuda_runtime.h>

#define BATCH 2048
#define TT    512
#define HID   64
#define NB    7       // rows per CTA (296 CTAs = exactly 2 per SM)
#define NCTA  296
#define NTHR  256

typedef unsigned long long u64;

__device__ __forceinline__ u64 ffma2(u64 a, u64 b, u64 c) {
    u64 d;
    asm("fma.rn.f32x2 %0, %1, %2, %3;" : "=l"(d) : "l"(a), "l"(b), "l"(c));
    return d;
}

__device__ __forceinline__ float sum2(u64 v) {
    float lo, hi;
    asm("mov.b64 {%0, %1}, %2;" : "=f"(lo), "=f"(hi) : "l"(v));
    return lo + hi;
}

__device__ __forceinline__ float tanh_fast(float v) {
    float r;
    asm("tanh.approx.f32 %0, %1;" : "=f"(r) : "f"(v));
    return r;
}

__global__ __launch_bounds__(NTHR, 2)
void lstm_kernel(const float* __restrict__ x,
                 const float* __restrict__ W_ih,
                 const float* __restrict__ W_hh,
                 const float* __restrict__ b_ih,
                 const float* __restrict__ b_hh,
                 const float* __restrict__ W_d,
                 const float* __restrict__ b_d,
                 float* __restrict__ out) {
    __shared__ float x_s[NB][TT];        // 14 KB
    __shared__ float h_s[NB][HID];       // 1.75 KB
    __shared__ float g_s[NB][4 * HID];   // 7 KB, interleaved: [r][4*m + gate]

    const int tid  = threadIdx.x;
    const int lane = tid & 31;
    const int warp = tid >> 5;                    // 0..7
    const int kh   = lane >> 4;                   // k-half: 0 -> k[0,32), 1 -> k[32,64)
    const int cp   = (warp << 4) | (lane & 15);   // column-pair id 0..127
    const int colA = cp;                          // i/f column (always sigmoid)
    const int colB = cp + 128;                    // g/o column
    const int mycol = kh ? colB : colA;           // column this thread finalizes
    const bool isTanh = (kh == 1) && (warp < 4);  // colB in g-range [128,192)
    // branchless activation: act(v) = s0 + s1*tanh(sc*v)
    const float s0 = isTanh ? 0.0f : 0.5f;
    const float s1 = isTanh ? 1.0f : 0.5f;
    const float sc = isTanh ? 1.0f : 0.5f;
    // interleaved g_s address for this thread's column
    const int gaddr = ((mycol & 63) << 2) | (mycol >> 6);

    const int row0 = blockIdx.x * NB;

    // --- weights: k-half of both owned columns (64 regs total, proven R8) ---
    u64 wA[16], wB[16];
    {
        const ulonglong2* pa = reinterpret_cast<const ulonglong2*>(W_hh + colA * HID + kh * 32);
        const ulonglong2* pb = reinterpret_cast<const ulonglong2*>(W_hh + colB * HID + kh * 32);
#pragma unroll
        for (int q = 0; q < 8; q++) {
            ulonglong2 va = pa[q];
            wA[2 * q + 0] = va.x;  wA[2 * q + 1] = va.y;
            ulonglong2 vb = pb[q];
            wB[2 * q + 0] = vb.x;  wB[2 * q + 1] = vb.y;
        }
    }
    const float bias = b_ih[mycol] + b_hh[mycol];
    const float wih  = W_ih[mycol];
    const int khoff  = kh * 32;

    // --- stage x slab (coalesced; clamp rows past BATCH) ---
    for (int i = tid; i < NB * TT; i += NTHR) {
        int r = i / TT;
        int t = i % TT;
        int gr = row0 + r;
        if (gr > BATCH - 1) gr = BATCH - 1;
        x_s[r][t] = x[gr * TT + t];
    }
    for (int i = tid; i < NB * HID; i += NTHR)
        ((float*)h_s)[i] = 0.0f;

    // --- phase-2 ownership ---
    // S0 = rows 0..2 (192 units): threads 0..191 own one unit each (c0)
    // S1 = rows 3..6 (256 units): all threads own one unit each (c1)
    float c0 = 0.0f, c1 = 0.0f;
    const bool hasS0 = (tid < 3 * HID);          // tid < 192
    const int r0a = tid >> 6,      m0 = tid & 63;   // rows 0..2
    const int r1a = 3 + (tid >> 6), m1 = tid & 63;  // rows 3..6

    __syncthreads();

    // ---- phase-1 body for one row (R8 datapath, verbatim) ----
#define P1_ROW(RR)                                                               \
    {                                                                            \
        const int r_ = (RR);                                                     \
        ulonglong2 hva[4], hvb[4];                                               \
        _Pragma("unroll")                                                        \
        for (int v = 0; v < 4; v++)                                              \
            hva[v] = *reinterpret_cast<const ulonglong2*>(&h_s[r_][khoff + v * 4]); \
        _Pragma("unroll")                                                        \
        for (int v = 0; v < 4; v++)                                              \
            hvb[v] = *reinterpret_cast<const ulonglong2*>(&h_s[r_][khoff + 16 + v * 4]); \
        u64 aA = 0ull, aB = 0ull;                                                \
        _Pragma("unroll")                                                        \
        for (int v = 0; v < 4; v++) {                                            \
            aA = ffma2(wA[2 * v + 0], hva[v].x, aA);                             \
            aA = ffma2(wA[2 * v + 1], hva[v].y, aA);                             \
            aB = ffma2(wB[2 * v + 0], hva[v].x, aB);                             \
            aB = ffma2(wB[2 * v + 1], hva[v].y, aB);                             \
        }                                                                        \
        _Pragma("unroll")                                                        \
        for (int v = 0; v < 4; v++) {                                            \
            aA = ffma2(wA[8 + 2 * v + 0], hvb[v].x, aA);                         \
            aA = ffma2(wA[8 + 2 * v + 1], hvb[v].y, aA);                         \
            aB = ffma2(wB[8 + 2 * v + 0], hvb[v].x, aB);                         \
            aB = ffma2(wB[8 + 2 * v + 1], hvb[v].y, aB);                         \
        }                                                                        \
        float pA = sum2(aA), pB = sum2(aB);                                      \
        float send = kh ? pA : pB;                                               \
        float recv = __shfl_xor_sync(0xffffffffu, send, 16);                     \
        float own  = kh ? pB : pA;                                               \
        float tot  = fmaf(x_s[r_][t], wih, bias) + own + recv;                   \
        g_s[r_][gaddr] = fmaf(s1, tanh_fast(sc * tot), s0);                      \
    }

    for (int t = 0; t < TT; t++) {
        // ---------- P1(S0): rows 0..2 ----------
#pragma unroll
        for (int r = 0; r < 3; r++) P1_ROW(r)
        __syncthreads();                       // g(S0) ready

        // ---------- P1(S1): rows 3..6  (queued ahead of P2(S0) loads) ----------
#pragma unroll
        for (int r = 3; r < NB; r++) P1_ROW(r)

        // ---------- P2(S0): rows 0..2 (overlaps P1(S1) tail) ----------
        if (hasS0) {
            float4 gv = *reinterpret_cast<const float4*>(&g_s[r0a][m0 << 2]);
            c0 = fmaf(gv.y, c0, gv.x * gv.z);          // f*c + i*g
            h_s[r0a][m0] = gv.w * tanh_fast(c0);       // o * tanh(c)
        }
        __syncthreads();                       // g(S1) + h(S0) ready

        // ---------- P2(S1): rows 3..6 (no barrier before next P1(S0): disjoint rows) ----
        {
            float4 gv = *reinterpret_cast<const float4*>(&g_s[r1a][m1 << 2]);
            c1 = fmaf(gv.y, c1, gv.x * gv.z);
            h_s[r1a][m1] = gv.w * tanh_fast(c1);
        }
    }
#undef P1_ROW

    // h(S1) written after last barrier: sync before projection reads all rows
    __syncthreads();

    // ---------- final projection ----------
    if (tid < NB && row0 + tid < BATCH) {
        float s = b_d[0];
#pragma unroll
        for (int mm = 0; mm < HID; mm++)
            s = fmaf(h_s[tid][mm], W_d[mm], s);
        out[row0 + tid] = s;
    }
}

extern "C" void kernel_launch(void* const* d_in, const int* in_sizes, int n_in,
                              void* d_out, int out_size) {
    const float* x    = (const float*)d_in[0];
    const float* W_ih = (const float*)d_in[1];
    const float* W_hh = (const float*)d_in[2];
    const float* b_ih = (const float*)d_in[3];
    const float* b_hh = (const float*)d_in[4];
    const float* W_d  = (const float*)d_in[5];
    const float* b_d  = (const float*)d_in[6];
    float* out = (float*)d_out;

    lstm_kernel<<<NCTA, NTHR>>>(x, W_ih, W_hh, b_ih, b_hh, W_d, b_d, out);
}